// round 3
// baseline (speedup 1.0000x reference)
#include <cuda_runtime.h>
#include <cstdint>
#include <cstddef>

// Problem constants (fixed by the dataset)
#define NB    4096          // batch
#define L2DIM 49            // (lmax+1)^2
#define CDIM  128           // channels
#define BAD   324           // 18*18 grid points
#define CP    64            // channel pairs (f32x2)

typedef unsigned long long ull;

// ---------------- f32x2 packed-fp32 helpers (sm_100+) ----------------
__device__ __forceinline__ ull ffma2(ull a, ull b, ull c) {
    ull d;
    asm("fma.rn.f32x2 %0, %1, %2, %3;" : "=l"(d) : "l"(a), "l"(b), "l"(c));
    return d;
}
__device__ __forceinline__ ull fmul2(ull a, ull b) {
    ull d;
    asm("mul.rn.f32x2 %0, %1, %2;" : "=l"(d) : "l"(a), "l"(b));
    return d;
}
__device__ __forceinline__ ull pack2(float x) {
    ull d;
    asm("mov.b64 %0, {%1, %1};" : "=l"(d) : "f"(x));
    return d;
}

// ---------------- scratch (static device globals; no allocation) ----------------
// Squared grid: [n][ba][c] fp32  (4096*324*128*4B = ~680 MB)
__device__ float g_G2[(size_t)NB * BAD * CDIM];
// W_from duplicated {w,w} for direct f32x2 broadcast loads: [ba][i]
__device__ float2 g_WFdup[BAD * L2DIM];

// ---------------- prep: duplicate W_from ----------------
__global__ void prep_kernel(const float* __restrict__ Wf) {
    int idx = blockIdx.x * blockDim.x + threadIdx.x;
    if (idx < BAD * L2DIM) {
        float w = Wf[idx];
        g_WFdup[idx] = make_float2(w, w);
    }
}

// ---------------- kernel A: grid = (W_to @ x)^2 ----------------
// One block = (one n) x (64-ba tile). 256 threads = 16 ba-groups x 16 c-groups.
// Thread computes a 4ba x 4cpair register tile in f32x2.
#define BA_TILE 64
__global__ void __launch_bounds__(256, 4)
kernelA(const float* __restrict__ X, const float* __restrict__ Wto) {
    __shared__ __align__(16) float  As[L2DIM][BA_TILE];  // W_to^T tile (zero-padded)
    __shared__ __align__(16) float2 Bs[L2DIM][CP];       // x[n] as channel pairs

    const int n       = blockIdx.y;
    const int ba_base = blockIdx.x * BA_TILE;
    const int tid     = threadIdx.x;

    // Stage W_to^T tile (transpose on the fly, zero-pad ba >= 324)
    for (int idx = tid; idx < L2DIM * BA_TILE; idx += 256) {
        int i = idx / BA_TILE, b = idx % BA_TILE;
        int ba = ba_base + b;
        As[i][b] = (ba < BAD) ? Wto[ba * L2DIM + i] : 0.0f;
    }
    // Stage x[n] (coalesced float2 loads)
    const float2* Xp = reinterpret_cast<const float2*>(X + (size_t)n * L2DIM * CDIM);
    for (int idx = tid; idx < L2DIM * CP; idx += 256) {
        Bs[idx / CP][idx % CP] = Xp[idx];
    }
    __syncthreads();

    const int cg = tid & 15;   // c-group: pairs cg*4 .. cg*4+3
    const int bg = tid >> 4;   // ba-group: bas bg*4 .. bg*4+3

    ull acc[4][4];
#pragma unroll
    for (int b = 0; b < 4; b++)
#pragma unroll
        for (int p = 0; p < 4; p++) acc[b][p] = 0ull;

#pragma unroll 7
    for (int i = 0; i < L2DIM; i++) {
        float4 wv = *reinterpret_cast<const float4*>(&As[i][bg * 4]);
        ull w0 = pack2(wv.x), w1 = pack2(wv.y), w2 = pack2(wv.z), w3 = pack2(wv.w);
        ulonglong2 q0 = *reinterpret_cast<const ulonglong2*>(&Bs[i][cg * 4]);
        ulonglong2 q1 = *reinterpret_cast<const ulonglong2*>(&Bs[i][cg * 4 + 2]);
        ull x0 = q0.x, x1 = q0.y, x2 = q1.x, x3 = q1.y;

        acc[0][0] = ffma2(w0, x0, acc[0][0]);
        acc[0][1] = ffma2(w0, x1, acc[0][1]);
        acc[0][2] = ffma2(w0, x2, acc[0][2]);
        acc[0][3] = ffma2(w0, x3, acc[0][3]);
        acc[1][0] = ffma2(w1, x0, acc[1][0]);
        acc[1][1] = ffma2(w1, x1, acc[1][1]);
        acc[1][2] = ffma2(w1, x2, acc[1][2]);
        acc[1][3] = ffma2(w1, x3, acc[1][3]);
        acc[2][0] = ffma2(w2, x0, acc[2][0]);
        acc[2][1] = ffma2(w2, x1, acc[2][1]);
        acc[2][2] = ffma2(w2, x2, acc[2][2]);
        acc[2][3] = ffma2(w2, x3, acc[2][3]);
        acc[3][0] = ffma2(w3, x0, acc[3][0]);
        acc[3][1] = ffma2(w3, x1, acc[3][1]);
        acc[3][2] = ffma2(w3, x2, acc[3][2]);
        acc[3][3] = ffma2(w3, x3, acc[3][3]);
    }

    // Square and store to G2
    ull* G2p = reinterpret_cast<ull*>(g_G2) + (size_t)n * BAD * CP;
#pragma unroll
    for (int b = 0; b < 4; b++) {
        int ba = ba_base + bg * 4 + b;
        if (ba < BAD) {
#pragma unroll
            for (int p = 0; p < 4; p++) {
                ull g = acc[b][p];
                G2p[(size_t)ba * CP + cg * 4 + p] = fmul2(g, g);
            }
        }
    }
}

// ---------------- kernel B: out = W_from^T @ grid^2 ----------------
// One block per n, 64 threads; thread owns one channel pair and all 49
// output coefficients as f32x2 register accumulators. W_from (duplicated)
// staged in SMEM in 54-ba tiles with padded stride 52 for LDS.128.
#define TB      54
#define WSTRIDE 52
__global__ void __launch_bounds__(64, 8)
kernelB(float* __restrict__ Out) {
    __shared__ __align__(16) float2 Wf_s[TB * WSTRIDE];

    const int n = blockIdx.x;
    const int t = threadIdx.x;

    ull acc[L2DIM];
#pragma unroll
    for (int i = 0; i < L2DIM; i++) acc[i] = 0ull;

    const ull* g2p = reinterpret_cast<const ull*>(g_G2) + (size_t)n * BAD * CP + t;

    for (int base = 0; base < BAD; base += TB) {
        __syncthreads();  // protect previous tile
        for (int idx = t; idx < TB * L2DIM; idx += 64) {
            Wf_s[(idx / L2DIM) * WSTRIDE + (idx % L2DIM)] = g_WFdup[base * L2DIM + idx];
        }
        __syncthreads();

        // depth-2 prefetch of the streamed G2 values
        ull gcur  = g2p[(size_t)base * CP];
        ull gnext = g2p[(size_t)(base + 1) * CP];
#pragma unroll 2
        for (int bb = 0; bb < TB; bb++) {
            ull g = gcur;
            gcur = gnext;
            if (bb + 2 < TB) gnext = g2p[(size_t)(base + bb + 2) * CP];

            const ulonglong2* wrow =
                reinterpret_cast<const ulonglong2*>(Wf_s + bb * WSTRIDE);
#pragma unroll
            for (int ii = 0; ii < 24; ii++) {
                ulonglong2 wp = wrow[ii];
                acc[2 * ii]     = ffma2(wp.x, g, acc[2 * ii]);
                acc[2 * ii + 1] = ffma2(wp.y, g, acc[2 * ii + 1]);
            }
            ull wlast = *reinterpret_cast<const ull*>(Wf_s + bb * WSTRIDE + 48);
            acc[48] = ffma2(wlast, g, acc[48]);
        }
    }

    ull* outp = reinterpret_cast<ull*>(Out) + (size_t)n * L2DIM * CP + t;
#pragma unroll
    for (int i = 0; i < L2DIM; i++) outp[(size_t)i * CP] = acc[i];
}

// ---------------- launcher ----------------
extern "C" void kernel_launch(void* const* d_in, const int* in_sizes, int n_in,
                              void* d_out, int out_size) {
    const float* X   = (const float*)d_in[0];  // inputs  (N, 49, 128)
    const float* Wto = (const float*)d_in[1];  // W_to    (18, 18, 49)
    const float* Wf  = (const float*)d_in[2];  // W_from  (18, 18, 49)
    float* Out = (float*)d_out;                // (N, 49, 128)

    prep_kernel<<<(BAD * L2DIM + 255) / 256, 256>>>(Wf);

    dim3 gA((BAD + BA_TILE - 1) / BA_TILE, NB);
    kernelA<<<gA, 256>>>(X, Wto);

    kernelB<<<NB, 64>>>(Out);
}

// round 4
// speedup vs baseline: 1.0006x; 1.0006x over previous
#include <cuda_runtime.h>
#include <cstdint>
#include <cstddef>

// Problem constants (fixed by the dataset)
#define NB    4096          // batch
#define L2DIM 49            // (lmax+1)^2
#define CDIM  128           // channels
#define BAD   324           // 18*18 grid points
#define CP    64            // channel pairs (f32x2)

typedef unsigned long long ull;

// ---------------- f32x2 packed-fp32 helpers (sm_100+) ----------------
__device__ __forceinline__ ull ffma2(ull a, ull b, ull c) {
    ull d;
    asm("fma.rn.f32x2 %0, %1, %2, %3;" : "=l"(d) : "l"(a), "l"(b), "l"(c));
    return d;
}
__device__ __forceinline__ ull fmul2(ull a, ull b) {
    ull d;
    asm("mul.rn.f32x2 %0, %1, %2;" : "=l"(d) : "l"(a), "l"(b));
    return d;
}
__device__ __forceinline__ ull pack2(float x) {
    ull d;
    asm("mov.b64 %0, {%1, %1};" : "=l"(d) : "f"(x));
    return d;
}

// ---------------- scratch (static device globals; no allocation) ----------------
// Squared grid: [n][ba][c] fp32  (4096*324*128*4B = ~680 MB)
__device__ float g_G2[(size_t)NB * BAD * CDIM];
// W_from duplicated {w,w} for direct f32x2 broadcast loads: [ba][i]
__device__ float2 g_WFdup[BAD * L2DIM];

// ---------------- prep: duplicate W_from ----------------
__global__ void prep_kernel(const float* __restrict__ Wf) {
    int idx = blockIdx.x * blockDim.x + threadIdx.x;
    if (idx < BAD * L2DIM) {
        float w = Wf[idx];
        g_WFdup[idx] = make_float2(w, w);
    }
}

// ---------------- kernel A: grid = (W_to @ x)^2 ----------------
// One block = (one n) x (64-ba tile). 256 threads = 16 ba-groups x 16 c-groups.
// Thread computes a 4ba x 4cpair register tile in f32x2.
#define BA_TILE 64
__global__ void __launch_bounds__(256, 4)
kernelA(const float* __restrict__ X, const float* __restrict__ Wto) {
    __shared__ __align__(16) float  As[L2DIM][BA_TILE];  // W_to^T tile (zero-padded)
    __shared__ __align__(16) float2 Bs[L2DIM][CP];       // x[n] as channel pairs

    const int n       = blockIdx.y;
    const int ba_base = blockIdx.x * BA_TILE;
    const int tid     = threadIdx.x;

    // Stage W_to^T tile (transpose on the fly, zero-pad ba >= 324)
    for (int idx = tid; idx < L2DIM * BA_TILE; idx += 256) {
        int i = idx / BA_TILE, b = idx % BA_TILE;
        int ba = ba_base + b;
        As[i][b] = (ba < BAD) ? Wto[ba * L2DIM + i] : 0.0f;
    }
    // Stage x[n] (coalesced float2 loads)
    const float2* Xp = reinterpret_cast<const float2*>(X + (size_t)n * L2DIM * CDIM);
    for (int idx = tid; idx < L2DIM * CP; idx += 256) {
        Bs[idx / CP][idx % CP] = Xp[idx];
    }
    __syncthreads();

    const int cg = tid & 15;   // c-group: pairs cg*4 .. cg*4+3
    const int bg = tid >> 4;   // ba-group: bas bg*4 .. bg*4+3

    ull acc[4][4];
#pragma unroll
    for (int b = 0; b < 4; b++)
#pragma unroll
        for (int p = 0; p < 4; p++) acc[b][p] = 0ull;

#pragma unroll 7
    for (int i = 0; i < L2DIM; i++) {
        float4 wv = *reinterpret_cast<const float4*>(&As[i][bg * 4]);
        ull w0 = pack2(wv.x), w1 = pack2(wv.y), w2 = pack2(wv.z), w3 = pack2(wv.w);
        ulonglong2 q0 = *reinterpret_cast<const ulonglong2*>(&Bs[i][cg * 4]);
        ulonglong2 q1 = *reinterpret_cast<const ulonglong2*>(&Bs[i][cg * 4 + 2]);
        ull x0 = q0.x, x1 = q0.y, x2 = q1.x, x3 = q1.y;

        acc[0][0] = ffma2(w0, x0, acc[0][0]);
        acc[0][1] = ffma2(w0, x1, acc[0][1]);
        acc[0][2] = ffma2(w0, x2, acc[0][2]);
        acc[0][3] = ffma2(w0, x3, acc[0][3]);
        acc[1][0] = ffma2(w1, x0, acc[1][0]);
        acc[1][1] = ffma2(w1, x1, acc[1][1]);
        acc[1][2] = ffma2(w1, x2, acc[1][2]);
        acc[1][3] = ffma2(w1, x3, acc[1][3]);
        acc[2][0] = ffma2(w2, x0, acc[2][0]);
        acc[2][1] = ffma2(w2, x1, acc[2][1]);
        acc[2][2] = ffma2(w2, x2, acc[2][2]);
        acc[2][3] = ffma2(w2, x3, acc[2][3]);
        acc[3][0] = ffma2(w3, x0, acc[3][0]);
        acc[3][1] = ffma2(w3, x1, acc[3][1]);
        acc[3][2] = ffma2(w3, x2, acc[3][2]);
        acc[3][3] = ffma2(w3, x3, acc[3][3]);
    }

    // Square and store to G2
    ull* G2p = reinterpret_cast<ull*>(g_G2) + (size_t)n * BAD * CP;
#pragma unroll
    for (int b = 0; b < 4; b++) {
        int ba = ba_base + bg * 4 + b;
        if (ba < BAD) {
#pragma unroll
            for (int p = 0; p < 4; p++) {
                ull g = acc[b][p];
                G2p[(size_t)ba * CP + cg * 4 + p] = fmul2(g, g);
            }
        }
    }
}

// ---------------- kernel B: out = W_from^T @ grid^2 ----------------
// One block per n, 64 threads; thread owns one channel pair and all 49
// output coefficients as f32x2 register accumulators. W_from (duplicated)
// staged in SMEM in 54-ba tiles with padded stride 52 for LDS.128.
#define TB      54
#define WSTRIDE 52
__global__ void __launch_bounds__(64, 8)
kernelB(float* __restrict__ Out) {
    __shared__ __align__(16) float2 Wf_s[TB * WSTRIDE];

    const int n = blockIdx.x;
    const int t = threadIdx.x;

    ull acc[L2DIM];
#pragma unroll
    for (int i = 0; i < L2DIM; i++) acc[i] = 0ull;

    const ull* g2p = reinterpret_cast<const ull*>(g_G2) + (size_t)n * BAD * CP + t;

    for (int base = 0; base < BAD; base += TB) {
        __syncthreads();  // protect previous tile
        for (int idx = t; idx < TB * L2DIM; idx += 64) {
            Wf_s[(idx / L2DIM) * WSTRIDE + (idx % L2DIM)] = g_WFdup[base * L2DIM + idx];
        }
        __syncthreads();

        // depth-2 prefetch of the streamed G2 values
        ull gcur  = g2p[(size_t)base * CP];
        ull gnext = g2p[(size_t)(base + 1) * CP];
#pragma unroll 2
        for (int bb = 0; bb < TB; bb++) {
            ull g = gcur;
            gcur = gnext;
            if (bb + 2 < TB) gnext = g2p[(size_t)(base + bb + 2) * CP];

            const ulonglong2* wrow =
                reinterpret_cast<const ulonglong2*>(Wf_s + bb * WSTRIDE);
#pragma unroll
            for (int ii = 0; ii < 24; ii++) {
                ulonglong2 wp = wrow[ii];
                acc[2 * ii]     = ffma2(wp.x, g, acc[2 * ii]);
                acc[2 * ii + 1] = ffma2(wp.y, g, acc[2 * ii + 1]);
            }
            ull wlast = *reinterpret_cast<const ull*>(Wf_s + bb * WSTRIDE + 48);
            acc[48] = ffma2(wlast, g, acc[48]);
        }
    }

    ull* outp = reinterpret_cast<ull*>(Out) + (size_t)n * L2DIM * CP + t;
#pragma unroll
    for (int i = 0; i < L2DIM; i++) outp[(size_t)i * CP] = acc[i];
}

// ---------------- launcher ----------------
extern "C" void kernel_launch(void* const* d_in, const int* in_sizes, int n_in,
                              void* d_out, int out_size) {
    const float* X   = (const float*)d_in[0];  // inputs  (N, 49, 128)
    const float* Wto = (const float*)d_in[1];  // W_to    (18, 18, 49)
    const float* Wf  = (const float*)d_in[2];  // W_from  (18, 18, 49)
    float* Out = (float*)d_out;                // (N, 49, 128)

    prep_kernel<<<(BAD * L2DIM + 255) / 256, 256>>>(Wf);

    dim3 gA((BAD + BA_TILE - 1) / BA_TILE, NB);
    kernelA<<<gA, 256>>>(X, Wto);

    kernelB<<<NB, 64>>>(Out);
}

// round 5
// speedup vs baseline: 1.0173x; 1.0167x over previous
#include <cuda_runtime.h>
#include <cstdint>
#include <cstddef>

// Problem constants (fixed by the dataset)
#define NB    4096          // batch
#define L2DIM 49            // (lmax+1)^2
#define CDIM  128           // channels
#define BAD   324           // 18*18 grid points
#define CP    64            // channel pairs (f32x2)
#define TBA   54            // ba tile (324 = 6*54 exactly)
#define NTILE 6
#define WSTR  50            // Ws row stride in float2 (400B, 16B aligned)
#define NTHR  448           // 7 groups x 64 channel-pairs

typedef unsigned long long ull;

// ---------------- f32x2 packed-fp32 helpers (sm_100+) ----------------
__device__ __forceinline__ ull ffma2(ull a, ull b, ull c) {
    ull d;
    asm("fma.rn.f32x2 %0, %1, %2, %3;" : "=l"(d) : "l"(a), "l"(b), "l"(c));
    return d;
}
__device__ __forceinline__ ull fmul2(ull a, ull b) {
    ull d;
    asm("mul.rn.f32x2 %0, %1, %2;" : "=l"(d) : "l"(a), "l"(b));
    return d;
}
__device__ __forceinline__ ull fadd2(ull a, ull b) {
    ull d;
    asm("add.rn.f32x2 %0, %1, %2;" : "=l"(d) : "l"(a), "l"(b));
    return d;
}

// ---------------- SMEM layout (dynamic, ~187 KB) ----------------
// [0)                G2s : 324 x 64 f32x2 (squared grid)    = 165888 B
// [165888)           Ws  : 54 x 50 f32x2 (dup weight tile)  =  21600 B
//                    Red : overlay on Ws for reduction, 7x7x64 f32x2 = 25088 B
#define G2S_OFF   0
#define WS_OFF    165888
#define RED_BYTES 25088
#define SMEM_BYTES (WS_OFF + RED_BYTES)   // 190976

__global__ void __launch_bounds__(NTHR, 1)
fused_kernel(const float* __restrict__ X,
             const float* __restrict__ Wto,
             const float* __restrict__ Wf,
             float* __restrict__ Out) {
    extern __shared__ __align__(16) char smem[];
    ull*    G2s = reinterpret_cast<ull*>(smem + G2S_OFF);
    float2* Ws  = reinterpret_cast<float2*>(smem + WS_OFF);
    ull*    Red = reinterpret_cast<ull*>(smem + WS_OFF);

    const int n   = blockIdx.x;
    const int tid = threadIdx.x;
    const int cp  = tid & 63;   // channel pair (uniform stride within warp)
    const int bg  = tid >> 6;   // group 0..6 (uniform within warp)

    // ---------- Phase 0: x[n] -> registers (49 f32x2 per thread) ----------
    const ull* Xu = reinterpret_cast<const ull*>(X) + (size_t)n * L2DIM * CP + cp;
    ull xreg[L2DIM];
#pragma unroll
    for (int i = 0; i < L2DIM; i++) xreg[i] = Xu[(size_t)i * CP];

    // ---------- Phase 1: G2s[ba][cp] = (sum_i Wto[ba][i] * x[i][cp])^2 ----------
    for (int t = 0; t < NTILE; t++) {
        __syncthreads();  // protect Ws from previous tile's readers
        // stage Wto tile, duplicated {w,w} for f32x2 broadcast
        for (int idx = tid; idx < TBA * L2DIM; idx += NTHR) {
            int r = idx / L2DIM, c = idx - r * L2DIM;
            float w = Wto[(size_t)(t * TBA + r) * L2DIM + c];
            Ws[r * WSTR + c] = make_float2(w, w);
        }
        __syncthreads();

#pragma unroll
        for (int k = 0; k < 8; k++) {
            int row = bg * 8 + k;            // uniform within warp
            if (row < TBA) {
                const ull* wrow = reinterpret_cast<const ull*>(Ws + row * WSTR);
                ull a0 = 0ull, a1 = 0ull;
#pragma unroll
                for (int ii = 0; ii < 24; ii++) {
                    ulonglong2 wp = reinterpret_cast<const ulonglong2*>(wrow)[ii];
                    a0 = ffma2(wp.x, xreg[2 * ii],     a0);
                    a1 = ffma2(wp.y, xreg[2 * ii + 1], a1);
                }
                a0 = ffma2(wrow[48], xreg[48], a0);
                ull g = fadd2(a0, a1);
                G2s[(t * TBA + row) * CP + cp] = fmul2(g, g);
            }
        }
    }

    // ---------- Phase 2: partial out[i][cp] over this group's ba rows ----------
    ull acc[L2DIM];
#pragma unroll
    for (int i = 0; i < L2DIM; i++) acc[i] = 0ull;

    for (int t = 0; t < NTILE; t++) {
        __syncthreads();  // Ws reuse / G2s writes complete
        for (int idx = tid; idx < TBA * L2DIM; idx += NTHR) {
            int r = idx / L2DIM, c = idx - r * L2DIM;
            float w = Wf[(size_t)(t * TBA + r) * L2DIM + c];
            Ws[r * WSTR + c] = make_float2(w, w);
        }
        __syncthreads();

#pragma unroll
        for (int k = 0; k < 8; k++) {
            int row = bg * 8 + k;
            if (row < TBA) {
                ull g2 = G2s[(t * TBA + row) * CP + cp];
                const ull* wrow = reinterpret_cast<const ull*>(Ws + row * WSTR);
#pragma unroll
                for (int ii = 0; ii < 24; ii++) {
                    ulonglong2 wp = reinterpret_cast<const ulonglong2*>(wrow)[ii];
                    acc[2 * ii]     = ffma2(wp.x, g2, acc[2 * ii]);
                    acc[2 * ii + 1] = ffma2(wp.y, g2, acc[2 * ii + 1]);
                }
                acc[48] = ffma2(wrow[48], g2, acc[48]);
            }
        }
    }

    // ---------- Phase 3: reduce 7 group-partials, write out ----------
    // 7 rounds of 7 coefficients each (49 = 7*7)
    ull* outp = reinterpret_cast<ull*>(Out) + (size_t)n * L2DIM * CP;
    const int rii = tid >> 6;   // coefficient-within-round this thread reduces
    const int rcp = tid & 63;
    for (int rnd = 0; rnd < 7; rnd++) {
        int i0 = rnd * 7;
        __syncthreads();  // Red reuse
#pragma unroll
        for (int ii = 0; ii < 7; ii++) {
            Red[((bg * 7 + ii) * CP) + cp] = acc[i0 + ii];
        }
        __syncthreads();
        ull s = Red[(0 * 7 + rii) * CP + rcp];
#pragma unroll
        for (int g = 1; g < 7; g++) {
            s = fadd2(s, Red[(g * 7 + rii) * CP + rcp]);
        }
        outp[(size_t)(i0 + rii) * CP + rcp] = s;
    }
}

// ---------------- launcher ----------------
extern "C" void kernel_launch(void* const* d_in, const int* in_sizes, int n_in,
                              void* d_out, int out_size) {
    const float* X   = (const float*)d_in[0];  // inputs  (N, 49, 128)
    const float* Wto = (const float*)d_in[1];  // W_to    (18, 18, 49)
    const float* Wf  = (const float*)d_in[2];  // W_from  (18, 18, 49)
    float* Out = (float*)d_out;                // (N, 49, 128)

    static bool attr_set = false;
    if (!attr_set) {
        cudaFuncSetAttribute(fused_kernel,
                             cudaFuncAttributeMaxDynamicSharedMemorySize,
                             SMEM_BYTES);
        attr_set = true;
    }

    fused_kernel<<<NB, NTHR, SMEM_BYTES>>>(X, Wto, Wf, Out);
}

// round 6
// speedup vs baseline: 1.2730x; 1.2514x over previous
#include <cuda_runtime.h>
#include <cstdint>
#include <cstddef>

// Problem constants
#define NB    4096
#define L2DIM 49
#define CDIM  128
#define BAD   324
#define CP    64            // channel pairs (f32x2)
#define NTHR  448

typedef unsigned long long ull;

__device__ __forceinline__ ull ffma2(ull a, ull b, ull c) {
    ull d;
    asm("fma.rn.f32x2 %0, %1, %2, %3;" : "=l"(d) : "l"(a), "l"(b), "l"(c));
    return d;
}
__device__ __forceinline__ ull fmul2(ull a, ull b) {
    ull d;
    asm("mul.rn.f32x2 %0, %1, %2;" : "=l"(d) : "l"(a), "l"(b));
    return d;
}
__device__ __forceinline__ ull fadd2(ull a, ull b) {
    ull d;
    asm("add.rn.f32x2 %0, %1, %2;" : "=l"(d) : "l"(a), "l"(b));
    return d;
}
__device__ __forceinline__ ull pack2(float x) {
    ull d;
    asm("mov.b64 %0, {%1, %1};" : "=l"(d) : "f"(x));
    return d;
}

// ---------------- SMEM layout ----------------
// [0)       G2s : 324 x 64 ull (squared grid, f32x2)      = 165888 B
// [165888)  Bs  : 49 x 64 ull (x[n] as f32x2 pairs)       =  25088 B
// [190976)  scratch:
//            phase1: As  float[49*114] (W_to^T tile)      =  22344 B
//            phase2: Wf_s float[2*81*58] (W_from tiles)   =  37584 B
//            phase3: Red ull[16*224]                      =  28672 B
#define BS_OFF      165888
#define SCR_OFF     190976
#define AS_STRIDE   114
#define WF_STRIDE   58
#define SMEM_BYTES  (190976 + 37584)   // 228560 <= 232448

__global__ void __launch_bounds__(NTHR, 1)
fused_kernel(const float* __restrict__ X,
             const float* __restrict__ Wto,
             const float* __restrict__ Wf,
             float* __restrict__ Out) {
    extern __shared__ __align__(16) char smem[];
    ull*    G2s  = reinterpret_cast<ull*>(smem);
    ull*    Bs   = reinterpret_cast<ull*>(smem + BS_OFF);
    float*  As   = reinterpret_cast<float*>(smem + SCR_OFF);
    float*  Wf_s = reinterpret_cast<float*>(smem + SCR_OFF);
    ull*    Red  = reinterpret_cast<ull*>(smem + SCR_OFF);

    const int n   = blockIdx.x;
    const int tid = threadIdx.x;
    const int cg  = tid & 7;     // channel-chunk group (8 per warp)

    // ---------- stage Bs: x[n] (49x128 fp32 = 1568 float4) ----------
    {
        const float4* Xv = reinterpret_cast<const float4*>(X + (size_t)n * L2DIM * CDIM);
        float4* Bv = reinterpret_cast<float4*>(Bs);
        for (int idx = tid; idx < L2DIM * 32; idx += NTHR) Bv[idx] = Xv[idx];
    }

    // ---------- Phase 1: G2s[ba][cp] = (sum_i Wto[ba][i] * x[i][cp])^2 ----------
    // thread = 2 rows x 8 cpairs. Chunk mapping: ull offset cg*2 + k*16 (k=0..3).
    const int rg = tid >> 3;     // 0..55 -> rows rg*2, rg*2+1 within pass
    for (int pass = 0; pass < 3; pass++) {
        const int base  = pass * 112;
        const int nrows = (pass == 2) ? 100 : 112;
        __syncthreads();
        // stage As[i][r] = Wto[(base+r)][i]  (coalesced global reads)
        for (int idx = tid; idx < nrows * L2DIM; idx += NTHR) {
            int r = idx / L2DIM, i = idx - r * L2DIM;
            As[i * AS_STRIDE + r] = Wto[(size_t)(base + r) * L2DIM + i];
        }
        __syncthreads();

        const int r0 = rg * 2;
        if (r0 < nrows) {
            ull acc[2][8];
#pragma unroll
            for (int d = 0; d < 2; d++)
#pragma unroll
                for (int c = 0; c < 8; c++) acc[d][c] = 0ull;

#pragma unroll 7
            for (int i = 0; i < L2DIM; i++) {
                float2 w = *reinterpret_cast<const float2*>(&As[i * AS_STRIDE + r0]);
                ull w0 = pack2(w.x), w1 = pack2(w.y);
                const ull* brow = Bs + i * CP + cg * 2;
                ulonglong2 x0 = *reinterpret_cast<const ulonglong2*>(brow);
                ulonglong2 x1 = *reinterpret_cast<const ulonglong2*>(brow + 16);
                ulonglong2 x2 = *reinterpret_cast<const ulonglong2*>(brow + 32);
                ulonglong2 x3 = *reinterpret_cast<const ulonglong2*>(brow + 48);
                acc[0][0] = ffma2(w0, x0.x, acc[0][0]);
                acc[0][1] = ffma2(w0, x0.y, acc[0][1]);
                acc[0][2] = ffma2(w0, x1.x, acc[0][2]);
                acc[0][3] = ffma2(w0, x1.y, acc[0][3]);
                acc[0][4] = ffma2(w0, x2.x, acc[0][4]);
                acc[0][5] = ffma2(w0, x2.y, acc[0][5]);
                acc[0][6] = ffma2(w0, x3.x, acc[0][6]);
                acc[0][7] = ffma2(w0, x3.y, acc[0][7]);
                acc[1][0] = ffma2(w1, x0.x, acc[1][0]);
                acc[1][1] = ffma2(w1, x0.y, acc[1][1]);
                acc[1][2] = ffma2(w1, x1.x, acc[1][2]);
                acc[1][3] = ffma2(w1, x1.y, acc[1][3]);
                acc[1][4] = ffma2(w1, x2.x, acc[1][4]);
                acc[1][5] = ffma2(w1, x2.y, acc[1][5]);
                acc[1][6] = ffma2(w1, x3.x, acc[1][6]);
                acc[1][7] = ffma2(w1, x3.y, acc[1][7]);
            }
            // square & store (same chunk mapping as phase-2 loads)
#pragma unroll
            for (int d = 0; d < 2; d++) {
                ull* grow = G2s + (size_t)(base + r0 + d) * CP + cg * 2;
#pragma unroll
                for (int k = 0; k < 4; k++) {
                    ulonglong2 v;
                    v.x = fmul2(acc[d][2 * k],     acc[d][2 * k]);
                    v.y = fmul2(acc[d][2 * k + 1], acc[d][2 * k + 1]);
                    *reinterpret_cast<ulonglong2*>(grow + k * 16) = v;
                }
            }
        }
    }

    // ---------- Phase 2: out[i][cp] = sum_ba Wf[ba][i] * G2s[ba][cp] ----------
    // 2 ba-ranges x 224 threads; thread = 2 coeffs x 8 cpairs.
    const int half = tid >= 224;                 // ba range (0: 0..161, 1: 162..323)
    const int ig   = (tid - half * 224) >> 3;    // 0..27 -> i = ig*2, ig*2+1

    ull acc[2][8];
#pragma unroll
    for (int d = 0; d < 2; d++)
#pragma unroll
        for (int c = 0; c < 8; c++) acc[d][c] = 0ull;

    for (int tile = 0; tile < 2; tile++) {
        __syncthreads();
        // stage both ranges' 81-ba tiles: Wf_s[buf][r][i], i zero-padded to 58
        for (int idx = tid; idx < 2 * 81 * WF_STRIDE; idx += NTHR) {
            int c  = idx % WF_STRIDE;
            int rr = idx / WF_STRIDE;        // 0..161
            int buf = rr / 81;
            int r   = rr - buf * 81;
            int ba  = buf * 162 + tile * 81 + r;
            Wf_s[idx] = (c < L2DIM) ? Wf[(size_t)ba * L2DIM + c] : 0.0f;
        }
        __syncthreads();

        const float* wbase = Wf_s + half * 81 * WF_STRIDE;
        const int ba0 = half * 162 + tile * 81;
#pragma unroll 3
        for (int r = 0; r < 81; r++) {
            float2 w = *reinterpret_cast<const float2*>(&wbase[r * WF_STRIDE + ig * 2]);
            ull w0 = pack2(w.x), w1 = pack2(w.y);
            const ull* grow = G2s + (size_t)(ba0 + r) * CP + cg * 2;
            ulonglong2 g0 = *reinterpret_cast<const ulonglong2*>(grow);
            ulonglong2 g1 = *reinterpret_cast<const ulonglong2*>(grow + 16);
            ulonglong2 g2 = *reinterpret_cast<const ulonglong2*>(grow + 32);
            ulonglong2 g3 = *reinterpret_cast<const ulonglong2*>(grow + 48);
            acc[0][0] = ffma2(w0, g0.x, acc[0][0]);
            acc[0][1] = ffma2(w0, g0.y, acc[0][1]);
            acc[0][2] = ffma2(w0, g1.x, acc[0][2]);
            acc[0][3] = ffma2(w0, g1.y, acc[0][3]);
            acc[0][4] = ffma2(w0, g2.x, acc[0][4]);
            acc[0][5] = ffma2(w0, g2.y, acc[0][5]);
            acc[0][6] = ffma2(w0, g3.x, acc[0][6]);
            acc[0][7] = ffma2(w0, g3.y, acc[0][7]);
            acc[1][0] = ffma2(w1, g0.x, acc[1][0]);
            acc[1][1] = ffma2(w1, g0.y, acc[1][1]);
            acc[1][2] = ffma2(w1, g1.x, acc[1][2]);
            acc[1][3] = ffma2(w1, g1.y, acc[1][3]);
            acc[1][4] = ffma2(w1, g2.x, acc[1][4]);
            acc[1][5] = ffma2(w1, g2.y, acc[1][5]);
            acc[1][6] = ffma2(w1, g3.x, acc[1][6]);
            acc[1][7] = ffma2(w1, g3.y, acc[1][7]);
        }
    }

    // ---------- Phase 3: 2-way reduction + writeout ----------
    __syncthreads();   // Wf_s tiles fully consumed; Red may overlay
    if (half) {
        const int t = tid - 224;
#pragma unroll
        for (int d = 0; d < 2; d++)
#pragma unroll
            for (int c = 0; c < 8; c++)
                Red[(d * 8 + c) * 224 + t] = acc[d][c];
    }
    __syncthreads();
    if (!half) {
        ull* outp = reinterpret_cast<ull*>(Out) + (size_t)n * L2DIM * CP;
#pragma unroll
        for (int d = 0; d < 2; d++) {
            int i = ig * 2 + d;
            if (i < L2DIM) {
#pragma unroll
                for (int k = 0; k < 4; k++) {
                    ulonglong2 v;
                    v.x = fadd2(acc[d][2 * k],     Red[(d * 8 + 2 * k) * 224 + tid]);
                    v.y = fadd2(acc[d][2 * k + 1], Red[(d * 8 + 2 * k + 1) * 224 + tid]);
                    *reinterpret_cast<ulonglong2*>(outp + (size_t)i * CP + cg * 2 + k * 16) = v;
                }
            }
        }
    }
}

// ---------------- launcher ----------------
extern "C" void kernel_launch(void* const* d_in, const int* in_sizes, int n_in,
                              void* d_out, int out_size) {
    const float* X   = (const float*)d_in[0];  // inputs  (N, 49, 128)
    const float* Wto = (const float*)d_in[1];  // W_to    (18, 18, 49)
    const float* Wf  = (const float*)d_in[2];  // W_from  (18, 18, 49)
    float* Out = (float*)d_out;                // (N, 49, 128)

    static bool attr_set = false;
    if (!attr_set) {
        cudaFuncSetAttribute(fused_kernel,
                             cudaFuncAttributeMaxDynamicSharedMemorySize,
                             SMEM_BYTES);
        attr_set = true;
    }

    fused_kernel<<<NB, NTHR, SMEM_BYTES>>>(X, Wto, Wf, Out);
}